// round 7
// baseline (speedup 1.0000x reference)
#include <cuda_runtime.h>
#include <cuda_fp16.h>
#include <cstdint>
#include <math.h>

// Router: logits = x @ Wg ; softmax ; top-2 ; renorm combine.
// x: [65536,1024] f32, Wg: [1024,64] f32.
// Out f32: [0,2T) combine | [2T,4T) idx | [4T,68T) probs.
//
// Single-product fp16 GEMM on mma.sync (fp32 accum): logit noise sigma ~3e-4.
// combine/probs tolerate that (threshold 1e-3); top-2 identity does not, so
// tokens with top-1/2 or 2/3 gap < 4e-3 (>9 sigma) are recomputed exactly in
// fp32 by a fix-up pass (~2% of tokens).

#define T_TOK 65536
#define D_DIM 1024
#define E_EXP 64
#define BM 128
#define KC 32
#define NKC (D_DIM / KC)   // 32
#define NTH 256
#define ASTRIDE 80         // bytes per smem row: 32 fp16 (64B) + 16B pad
#define TH_AMB 4.0e-3f
#define NEG_INF (-3.0e38f)

__device__ __half g_wth[E_EXP * D_DIM];  // Wg^T fp16: [n][k]
__device__ int g_cnt;
__device__ int g_list[T_TOK];

// ---------- helpers ----------
__device__ __forceinline__ uint32_t pack2(float a, float b) {
    __half2 H = __floats2half2_rn(a, b);
    return *(uint32_t*)&H;
}

__device__ __forceinline__ void ldm4(uint32_t& r0, uint32_t& r1, uint32_t& r2,
                                     uint32_t& r3, uint32_t addr) {
    asm volatile("ldmatrix.sync.aligned.m8n8.x4.shared.b16 {%0,%1,%2,%3}, [%4];"
                 : "=r"(r0), "=r"(r1), "=r"(r2), "=r"(r3) : "r"(addr));
}

__device__ __forceinline__ void mma_f16(float* c, uint32_t a0, uint32_t a1,
                                        uint32_t a2, uint32_t a3,
                                        uint32_t b0, uint32_t b1) {
    asm volatile(
        "mma.sync.aligned.m16n8k16.row.col.f32.f16.f16.f32 "
        "{%0,%1,%2,%3}, {%4,%5,%6,%7}, {%8,%9}, {%0,%1,%2,%3};"
        : "+f"(c[0]), "+f"(c[1]), "+f"(c[2]), "+f"(c[3])
        : "r"(a0), "r"(a1), "r"(a2), "r"(a3), "r"(b0), "r"(b1));
}

// insert (v,i) into descending top-3, lower-index tie-break (jax top_k order)
__device__ __forceinline__ void ins3(float v, int i,
                                     float& v1, int& i1, float& v2, int& i2,
                                     float& v3, int& i3) {
    if (v > v1 || (v == v1 && i < i1)) {
        v3 = v2; i3 = i2; v2 = v1; i2 = i1; v1 = v; i1 = i;
    } else if (v > v2 || (v == v2 && i < i2)) {
        v3 = v2; i3 = i2; v2 = v; i2 = i;
    } else if (v > v3 || (v == v3 && i < i3)) {
        v3 = v; i3 = i;
    }
}

// ---------- prep: Wg -> fp16 transpose; zero counter ----------
__global__ void prep(const float* __restrict__ Wg) {
    int i = blockIdx.x * blockDim.x + threadIdx.x;  // 0..65535
    int k = i >> 6, n = i & 63;
    g_wth[n * D_DIM + k] = __float2half_rn(Wg[i]);
    if (i == 0) g_cnt = 0;
}

// ---------- pass 1 ----------
__global__ __launch_bounds__(NTH, 3)
void router_main(const float* __restrict__ x, float* __restrict__ out) {
    __shared__ __align__(16) unsigned char sA[BM * ASTRIDE];     // 10240 B
    __shared__ __align__(16) unsigned char sB[E_EXP * ASTRIDE];  //  5120 B

    const int tid = threadIdx.x;
    const int w   = tid >> 5;
    const int lid = tid & 31;
    const int m0  = blockIdx.x * BM;

    const uint32_t sAu = (uint32_t)__cvta_generic_to_shared(sA);
    const uint32_t sBu = (uint32_t)__cvta_generic_to_shared(sB);

    float acc[8][4];
    #pragma unroll
    for (int t = 0; t < 8; ++t)
        #pragma unroll
        for (int c = 0; c < 4; ++c) acc[t][c] = 0.0f;

    const float* xbase = x + (size_t)m0 * D_DIM;

    // prefetch chunk 0
    float4 pa[4]; float4 pb;
    #pragma unroll
    for (int i = 0; i < 4; ++i) {
        int lin = i * NTH + tid;
        pa[i] = *(const float4*)(xbase + (size_t)(lin >> 3) * D_DIM + (lin & 7) * 4);
    }
    pb = ((const float4*)(g_wth + (size_t)(tid >> 2) * D_DIM))[tid & 3];

    for (int kt = 0; kt < NKC; ++kt) {
        // stage prefetched tiles into smem (fp32 -> fp16 on the fly for A)
        #pragma unroll
        for (int i = 0; i < 4; ++i) {
            int lin = i * NTH + tid;
            uint32_t p0 = pack2(pa[i].x, pa[i].y);
            uint32_t p1 = pack2(pa[i].z, pa[i].w);
            *(uint2*)(sA + (lin >> 3) * ASTRIDE + (lin & 7) * 8) = make_uint2(p0, p1);
        }
        *(float4*)(sB + (tid >> 2) * ASTRIDE + (tid & 3) * 16) = pb;
        __syncthreads();

        if (kt + 1 < NKC) {
            const int k0 = (kt + 1) * KC;
            #pragma unroll
            for (int i = 0; i < 4; ++i) {
                int lin = i * NTH + tid;
                pa[i] = *(const float4*)(xbase + (size_t)(lin >> 3) * D_DIM + k0 + (lin & 7) * 4);
            }
            pb = ((const float4*)(g_wth + (size_t)(tid >> 2) * D_DIM + k0))[tid & 3];
        }

        // compute: 2 k16-steps
        #pragma unroll
        for (int ks = 0; ks < 2; ++ks) {
            const int m = lid >> 3, r = lid & 7;
            uint32_t a0, a1, a2, a3;
            {
                uint32_t addr = sAu + (w * 16 + (m & 1) * 8 + r) * ASTRIDE
                              + (ks * 16 + (m >> 1) * 8) * 2;
                ldm4(a0, a1, a2, a3, addr);
            }
            uint32_t b[16];
            #pragma unroll
            for (int j = 0; j < 4; ++j) {
                uint32_t addr = sBu + (j * 16 + (m >> 1) * 8 + r) * ASTRIDE
                              + (ks * 16 + (m & 1) * 8) * 2;
                ldm4(b[4 * j], b[4 * j + 1], b[4 * j + 2], b[4 * j + 3], addr);
            }
            #pragma unroll
            for (int t = 0; t < 8; ++t)
                mma_f16(acc[t], a0, a1, a2, a3, b[2 * t], b[2 * t + 1]);
        }
        __syncthreads();
    }

    // ---------- fused epilogue ----------
    const int q = lid >> 2;   // row within warp tile half
    const int c = lid & 3;    // column quad lane

    #pragma unroll
    for (int rr = 0; rr < 2; ++rr) {
        float v1 = NEG_INF, v2 = NEG_INF, v3 = NEG_INF;
        int   i1 = 0, i2 = 0, i3 = 0;
        #pragma unroll
        for (int t = 0; t < 8; ++t) {
            ins3(acc[t][rr * 2 + 0], t * 8 + c * 2 + 0, v1, i1, v2, i2, v3, i3);
            ins3(acc[t][rr * 2 + 1], t * 8 + c * 2 + 1, v1, i1, v2, i2, v3, i3);
        }
        #pragma unroll
        for (int d = 1; d <= 2; d <<= 1) {
            float ov1 = __shfl_xor_sync(0xffffffffu, v1, d);
            float ov2 = __shfl_xor_sync(0xffffffffu, v2, d);
            float ov3 = __shfl_xor_sync(0xffffffffu, v3, d);
            int   oi1 = __shfl_xor_sync(0xffffffffu, i1, d);
            int   oi2 = __shfl_xor_sync(0xffffffffu, i2, d);
            int   oi3 = __shfl_xor_sync(0xffffffffu, i3, d);
            ins3(ov1, oi1, v1, i1, v2, i2, v3, i3);
            ins3(ov2, oi2, v1, i1, v2, i2, v3, i3);
            ins3(ov3, oi3, v1, i1, v2, i2, v3, i3);
        }
        float s = 0.0f;
        #pragma unroll
        for (int t = 0; t < 8; ++t) {
            float e0 = expf(acc[t][rr * 2 + 0] - v1);
            float e1 = expf(acc[t][rr * 2 + 1] - v1);
            acc[t][rr * 2 + 0] = e0;
            acc[t][rr * 2 + 1] = e1;
            s += e0 + e1;
        }
        s += __shfl_xor_sync(0xffffffffu, s, 1);
        s += __shfl_xor_sync(0xffffffffu, s, 2);
        const float inv = 1.0f / s;

        const int gt = m0 + w * 16 + q + rr * 8;
        float* pr = out + (size_t)T_TOK * 4 + (size_t)gt * E_EXP;
        #pragma unroll
        for (int t = 0; t < 8; ++t) {
            *(float2*)(pr + t * 8 + c * 2) =
                make_float2(acc[t][rr * 2] * inv, acc[t][rr * 2 + 1] * inv);
        }
        if (c == 0) {
            float e2 = expf(v2 - v1);
            float cd = 1.0f / (1.0f + e2);
            *(float2*)(out + (size_t)gt * 2) = make_float2(cd, e2 * cd);
            *(float2*)(out + (size_t)T_TOK * 2 + (size_t)gt * 2) =
                make_float2((float)i1, (float)i2);
            if ((v1 - v2 < TH_AMB) || (v2 - v3 < TH_AMB)) {
                int p = atomicAdd(&g_cnt, 1);
                g_list[p] = gt;
            }
        }
    }
}

// ---------- pass 2: exact fp32 fix-up for ambiguous tokens ----------
__global__ __launch_bounds__(128)
void router_fixup(const float* __restrict__ x, const float* __restrict__ Wg,
                  float* __restrict__ out) {
    const int lid = threadIdx.x & 31;
    const int gw  = (blockIdx.x * blockDim.x + threadIdx.x) >> 5;
    const int nw  = (gridDim.x * blockDim.x) >> 5;
    const int cnt = g_cnt;
    const float2* W2 = (const float2*)Wg;  // [1024][32] expert pairs

    for (int idx = gw; idx < cnt; idx += nw) {
        const int t = g_list[idx];
        const float* xr = x + (size_t)t * D_DIM;
        float ax = 0.0f, ay = 0.0f;  // experts 2*lid, 2*lid+1
        for (int k0 = 0; k0 < D_DIM; k0 += 32) {
            float xv = xr[k0 + lid];
            #pragma unroll
            for (int kk = 0; kk < 32; ++kk) {
                float v = __shfl_sync(0xffffffffu, xv, kk);
                float2 wv = W2[(size_t)(k0 + kk) * 32 + lid];
                ax = fmaf(v, wv.x, ax);
                ay = fmaf(v, wv.y, ay);
            }
        }
        float v1 = NEG_INF, v2 = NEG_INF, v3 = NEG_INF;
        int   i1 = 0, i2 = 0, i3 = 0;
        ins3(ax, 2 * lid + 0, v1, i1, v2, i2, v3, i3);
        ins3(ay, 2 * lid + 1, v1, i1, v2, i2, v3, i3);
        #pragma unroll
        for (int d = 1; d < 32; d <<= 1) {
            float ov1 = __shfl_xor_sync(0xffffffffu, v1, d);
            float ov2 = __shfl_xor_sync(0xffffffffu, v2, d);
            float ov3 = __shfl_xor_sync(0xffffffffu, v3, d);
            int   oi1 = __shfl_xor_sync(0xffffffffu, i1, d);
            int   oi2 = __shfl_xor_sync(0xffffffffu, i2, d);
            int   oi3 = __shfl_xor_sync(0xffffffffu, i3, d);
            ins3(ov1, oi1, v1, i1, v2, i2, v3, i3);
            ins3(ov2, oi2, v1, i1, v2, i2, v3, i3);
            ins3(ov3, oi3, v1, i1, v2, i2, v3, i3);
        }
        float ex = expf(ax - v1), ey = expf(ay - v1);
        float s = ex + ey;
        #pragma unroll
        for (int d = 1; d < 32; d <<= 1) s += __shfl_xor_sync(0xffffffffu, s, d);
        const float inv = 1.0f / s;

        *(float2*)(out + (size_t)T_TOK * 4 + (size_t)t * E_EXP + 2 * lid) =
            make_float2(ex * inv, ey * inv);
        if (lid == 0) {
            float e2 = expf(v2 - v1);
            float cd = 1.0f / (1.0f + e2);
            *(float2*)(out + (size_t)t * 2) = make_float2(cd, e2 * cd);
            *(float2*)(out + (size_t)T_TOK * 2 + (size_t)t * 2) =
                make_float2((float)i1, (float)i2);
        }
    }
}

extern "C" void kernel_launch(void* const* d_in, const int* in_sizes, int n_in,
                              void* d_out, int out_size) {
    const float* x  = (const float*)d_in[0];
    const float* Wg = (const float*)d_in[1];
    float* out = (float*)d_out;
    (void)in_sizes; (void)n_in; (void)out_size;

    prep<<<256, 256>>>(Wg);
    router_main<<<T_TOK / BM, NTH>>>(x, out);
    router_fixup<<<256, 128>>>(x, Wg, out);
}

// round 8
// speedup vs baseline: 1.3686x; 1.3686x over previous
#include <cuda_runtime.h>
#include <cuda_fp16.h>
#include <cstdint>
#include <math.h>

// Router: logits = x @ Wg ; softmax ; top-2 ; renorm combine.
// x: [65536,1024] f32, Wg: [1024,64] f32.
// Out f32: [0,2T) combine | [2T,4T) idx | [4T,68T) probs.
//
// 2-product fp16 mma.sync (A_hi*B_hi + A_hi*B_lo), fp32 accum.
// KC=64, 2-stage smem ping-pong (2 syncs/chunk, 16 chunks), A+B register
// prefetch one chunk ahead. fp32 fix-up for tokens with top gaps < 2e-3.

#define T_TOK 65536
#define D_DIM 1024
#define E_EXP 64
#define BM 128
#define KC 64
#define NKC (D_DIM / KC)   // 16
#define NTH 256
#define ASTRIDE 144        // 64 fp16 (128B) + 16B pad; conflict-free ldmatrix
#define TH_AMB 2.0e-3f
#define NEG_INF (-3.0e38f)

#define A_BYTES (BM * ASTRIDE)       // 18432
#define B_BYTES (E_EXP * ASTRIDE)    //  9216
#define STAGE_BYTES (A_BYTES + 2 * B_BYTES)   // 36864
#define SMEM_TOTAL (2 * STAGE_BYTES)          // 73728

__device__ __half g_wth[E_EXP * D_DIM];  // Wg^T hi: [n][k]
__device__ __half g_wtl[E_EXP * D_DIM];  // Wg^T lo (residual): [n][k]
__device__ int g_cnt;
__device__ int g_list[T_TOK];

// ---------- helpers ----------
__device__ __forceinline__ uint32_t pack2(float a, float b) {
    __half2 H = __floats2half2_rn(a, b);
    return *(uint32_t*)&H;
}

__device__ __forceinline__ void ldm4(uint32_t& r0, uint32_t& r1, uint32_t& r2,
                                     uint32_t& r3, uint32_t addr) {
    asm volatile("ldmatrix.sync.aligned.m8n8.x4.shared.b16 {%0,%1,%2,%3}, [%4];"
                 : "=r"(r0), "=r"(r1), "=r"(r2), "=r"(r3) : "r"(addr));
}

__device__ __forceinline__ void mma_f16(float* c, uint32_t a0, uint32_t a1,
                                        uint32_t a2, uint32_t a3,
                                        uint32_t b0, uint32_t b1) {
    asm volatile(
        "mma.sync.aligned.m16n8k16.row.col.f32.f16.f16.f32 "
        "{%0,%1,%2,%3}, {%4,%5,%6,%7}, {%8,%9}, {%0,%1,%2,%3};"
        : "+f"(c[0]), "+f"(c[1]), "+f"(c[2]), "+f"(c[3])
        : "r"(a0), "r"(a1), "r"(a2), "r"(a3), "r"(b0), "r"(b1));
}

__device__ __forceinline__ void ins3(float v, int i,
                                     float& v1, int& i1, float& v2, int& i2,
                                     float& v3, int& i3) {
    if (v > v1 || (v == v1 && i < i1)) {
        v3 = v2; i3 = i2; v2 = v1; i2 = i1; v1 = v; i1 = i;
    } else if (v > v2 || (v == v2 && i < i2)) {
        v3 = v2; i3 = i2; v2 = v; i2 = i;
    } else if (v > v3 || (v == v3 && i < i3)) {
        v3 = v; i3 = i;
    }
}

// ---------- prep ----------
__global__ void prep(const float* __restrict__ Wg) {
    int i = blockIdx.x * blockDim.x + threadIdx.x;  // 0..65535
    int k = i >> 6, n = i & 63;
    float w = Wg[i];
    __half h = __float2half_rn(w);
    __half l = __float2half_rn(w - __half2float(h));
    g_wth[n * D_DIM + k] = h;
    g_wtl[n * D_DIM + k] = l;
    if (i == 0) g_cnt = 0;
}

// ---------- pass 1 ----------
__global__ __launch_bounds__(NTH, 2)
void router_main(const float* __restrict__ x, float* __restrict__ out) {
    extern __shared__ __align__(16) unsigned char smem[];
    unsigned char* sA[2] = { smem, smem + STAGE_BYTES };
    unsigned char* sBh[2] = { smem + A_BYTES, smem + STAGE_BYTES + A_BYTES };
    unsigned char* sBl[2] = { smem + A_BYTES + B_BYTES,
                              smem + STAGE_BYTES + A_BYTES + B_BYTES };

    const int tid = threadIdx.x;
    const int w   = tid >> 5;
    const int lid = tid & 31;
    const int m0  = blockIdx.x * BM;

    float acc[8][4];
    #pragma unroll
    for (int t = 0; t < 8; ++t)
        #pragma unroll
        for (int c = 0; c < 4; ++c) acc[t][c] = 0.0f;

    const float* xbase = x + (size_t)m0 * D_DIM;

    // A load mapping: 8 float4/thread, row = lin>>4, c4 = lin&15
    // B load mapping: 2 float4/thread/mat, row = lin>>3, c = lin&7
    float4 pa[8];
    float4 pbh[2], pbl[2];

    // ---- prologue: chunk 0 -> stage 0; prefetch chunk 1 ----
    #pragma unroll
    for (int i = 0; i < 8; ++i) {
        int lin = i * NTH + tid;
        pa[i] = *(const float4*)(xbase + (size_t)(lin >> 4) * D_DIM + (lin & 15) * 4);
    }
    #pragma unroll
    for (int i = 0; i < 2; ++i) {
        int lin = i * NTH + tid;
        pbh[i] = *(const float4*)(g_wth + (size_t)(lin >> 3) * D_DIM + (lin & 7) * 8);
        pbl[i] = *(const float4*)(g_wtl + (size_t)(lin >> 3) * D_DIM + (lin & 7) * 8);
    }
    #pragma unroll
    for (int i = 0; i < 8; ++i) {
        int lin = i * NTH + tid;
        uint32_t p0 = pack2(pa[i].x, pa[i].y);
        uint32_t p1 = pack2(pa[i].z, pa[i].w);
        *(uint2*)(sA[0] + (lin >> 4) * ASTRIDE + (lin & 15) * 8) = make_uint2(p0, p1);
    }
    #pragma unroll
    for (int i = 0; i < 2; ++i) {
        int lin = i * NTH + tid;
        int off = (lin >> 3) * ASTRIDE + (lin & 7) * 16;
        *(float4*)(sBh[0] + off) = pbh[i];
        *(float4*)(sBl[0] + off) = pbl[i];
    }
    // prefetch chunk 1
    #pragma unroll
    for (int i = 0; i < 8; ++i) {
        int lin = i * NTH + tid;
        pa[i] = *(const float4*)(xbase + (size_t)(lin >> 4) * D_DIM + KC + (lin & 15) * 4);
    }
    #pragma unroll
    for (int i = 0; i < 2; ++i) {
        int lin = i * NTH + tid;
        pbh[i] = *(const float4*)(g_wth + (size_t)(lin >> 3) * D_DIM + KC + (lin & 7) * 8);
        pbl[i] = *(const float4*)(g_wtl + (size_t)(lin >> 3) * D_DIM + KC + (lin & 7) * 8);
    }

    for (int kt = 0; kt < NKC; ++kt) {
        const int cur = kt & 1;
        if (kt + 1 < NKC) {
            const int nxt = (kt + 1) & 1;
            // stage chunk kt+1 from prefetch regs
            #pragma unroll
            for (int i = 0; i < 8; ++i) {
                int lin = i * NTH + tid;
                uint32_t p0 = pack2(pa[i].x, pa[i].y);
                uint32_t p1 = pack2(pa[i].z, pa[i].w);
                *(uint2*)(sA[nxt] + (lin >> 4) * ASTRIDE + (lin & 15) * 8) =
                    make_uint2(p0, p1);
            }
            #pragma unroll
            for (int i = 0; i < 2; ++i) {
                int lin = i * NTH + tid;
                int off = (lin >> 3) * ASTRIDE + (lin & 7) * 16;
                *(float4*)(sBh[nxt] + off) = pbh[i];
                *(float4*)(sBl[nxt] + off) = pbl[i];
            }
            if (kt + 2 < NKC) {
                const int k0 = (kt + 2) * KC;
                #pragma unroll
                for (int i = 0; i < 8; ++i) {
                    int lin = i * NTH + tid;
                    pa[i] = *(const float4*)(xbase + (size_t)(lin >> 4) * D_DIM
                                             + k0 + (lin & 15) * 4);
                }
                #pragma unroll
                for (int i = 0; i < 2; ++i) {
                    int lin = i * NTH + tid;
                    pbh[i] = *(const float4*)(g_wth + (size_t)(lin >> 3) * D_DIM
                                              + k0 + (lin & 7) * 8);
                    pbl[i] = *(const float4*)(g_wtl + (size_t)(lin >> 3) * D_DIM
                                              + k0 + (lin & 7) * 8);
                }
            }
        }
        __syncthreads();   // staged data visible; prev readers done

        const uint32_t sAu  = (uint32_t)__cvta_generic_to_shared(sA[cur]);
        const uint32_t sBhu = (uint32_t)__cvta_generic_to_shared(sBh[cur]);
        const uint32_t sBlu = (uint32_t)__cvta_generic_to_shared(sBl[cur]);
        const int m = lid >> 3, r = lid & 7;

        #pragma unroll
        for (int ks = 0; ks < 4; ++ks) {
            uint32_t a0, a1, a2, a3;
            {
                uint32_t addr = sAu + (w * 16 + (m & 1) * 8 + r) * ASTRIDE
                              + (ks * 16 + (m >> 1) * 8) * 2;
                ldm4(a0, a1, a2, a3, addr);
            }
            uint32_t bh[16], bl[16];
            #pragma unroll
            for (int j = 0; j < 4; ++j) {
                uint32_t boff = (j * 16 + (m >> 1) * 8 + r) * ASTRIDE
                              + (ks * 16 + (m & 1) * 8) * 2;
                ldm4(bh[4 * j], bh[4 * j + 1], bh[4 * j + 2], bh[4 * j + 3], sBhu + boff);
                ldm4(bl[4 * j], bl[4 * j + 1], bl[4 * j + 2], bl[4 * j + 3], sBlu + boff);
            }
            #pragma unroll
            for (int t = 0; t < 8; ++t) {
                mma_f16(acc[t], a0, a1, a2, a3, bh[2 * t], bh[2 * t + 1]);
                mma_f16(acc[t], a0, a1, a2, a3, bl[2 * t], bl[2 * t + 1]);
            }
        }
        __syncthreads();   // done reading stage cur (overwritten at kt+2 staging)
    }

    // ---------- fused epilogue ----------
    const int q = lid >> 2;
    const int c = lid & 3;

    #pragma unroll
    for (int rr = 0; rr < 2; ++rr) {
        float v1 = NEG_INF, v2 = NEG_INF, v3 = NEG_INF;
        int   i1 = 0, i2 = 0, i3 = 0;
        #pragma unroll
        for (int t = 0; t < 8; ++t) {
            ins3(acc[t][rr * 2 + 0], t * 8 + c * 2 + 0, v1, i1, v2, i2, v3, i3);
            ins3(acc[t][rr * 2 + 1], t * 8 + c * 2 + 1, v1, i1, v2, i2, v3, i3);
        }
        #pragma unroll
        for (int d = 1; d <= 2; d <<= 1) {
            float ov1 = __shfl_xor_sync(0xffffffffu, v1, d);
            float ov2 = __shfl_xor_sync(0xffffffffu, v2, d);
            float ov3 = __shfl_xor_sync(0xffffffffu, v3, d);
            int   oi1 = __shfl_xor_sync(0xffffffffu, i1, d);
            int   oi2 = __shfl_xor_sync(0xffffffffu, i2, d);
            int   oi3 = __shfl_xor_sync(0xffffffffu, i3, d);
            ins3(ov1, oi1, v1, i1, v2, i2, v3, i3);
            ins3(ov2, oi2, v1, i1, v2, i2, v3, i3);
            ins3(ov3, oi3, v1, i1, v2, i2, v3, i3);
        }
        float s = 0.0f;
        #pragma unroll
        for (int t = 0; t < 8; ++t) {
            float e0 = expf(acc[t][rr * 2 + 0] - v1);
            float e1 = expf(acc[t][rr * 2 + 1] - v1);
            acc[t][rr * 2 + 0] = e0;
            acc[t][rr * 2 + 1] = e1;
            s += e0 + e1;
        }
        s += __shfl_xor_sync(0xffffffffu, s, 1);
        s += __shfl_xor_sync(0xffffffffu, s, 2);
        const float inv = 1.0f / s;

        const int gt = m0 + w * 16 + q + rr * 8;
        float* pr = out + (size_t)T_TOK * 4 + (size_t)gt * E_EXP;
        #pragma unroll
        for (int t = 0; t < 8; ++t) {
            *(float2*)(pr + t * 8 + c * 2) =
                make_float2(acc[t][rr * 2] * inv, acc[t][rr * 2 + 1] * inv);
        }
        if (c == 0) {
            float e2 = expf(v2 - v1);
            float cd = 1.0f / (1.0f + e2);
            *(float2*)(out + (size_t)gt * 2) = make_float2(cd, e2 * cd);
            *(float2*)(out + (size_t)T_TOK * 2 + (size_t)gt * 2) =
                make_float2((float)i1, (float)i2);
            if ((v1 - v2 < TH_AMB) || (v2 - v3 < TH_AMB)) {
                int p = atomicAdd(&g_cnt, 1);
                g_list[p] = gt;
            }
        }
    }
}

// ---------- pass 2: exact fp32 fix-up ----------
__global__ __launch_bounds__(128)
void router_fixup(const float* __restrict__ x, const float* __restrict__ Wg,
                  float* __restrict__ out) {
    const int lid = threadIdx.x & 31;
    const int gw  = (blockIdx.x * blockDim.x + threadIdx.x) >> 5;
    const int nw  = (gridDim.x * blockDim.x) >> 5;
    const int cnt = g_cnt;
    const float2* W2 = (const float2*)Wg;

    for (int idx = gw; idx < cnt; idx += nw) {
        const int t = g_list[idx];
        const float* xr = x + (size_t)t * D_DIM;
        float ax = 0.0f, ay = 0.0f;
        for (int k0 = 0; k0 < D_DIM; k0 += 32) {
            float xv = xr[k0 + lid];
            #pragma unroll
            for (int kk = 0; kk < 32; ++kk) {
                float v = __shfl_sync(0xffffffffu, xv, kk);
                float2 wv = W2[(size_t)(k0 + kk) * 32 + lid];
                ax = fmaf(v, wv.x, ax);
                ay = fmaf(v, wv.y, ay);
            }
        }
        float v1 = NEG_INF, v2 = NEG_INF, v3 = NEG_INF;
        int   i1 = 0, i2 = 0, i3 = 0;
        ins3(ax, 2 * lid + 0, v1, i1, v2, i2, v3, i3);
        ins3(ay, 2 * lid + 1, v1, i1, v2, i2, v3, i3);
        #pragma unroll
        for (int d = 1; d < 32; d <<= 1) {
            float ov1 = __shfl_xor_sync(0xffffffffu, v1, d);
            float ov2 = __shfl_xor_sync(0xffffffffu, v2, d);
            float ov3 = __shfl_xor_sync(0xffffffffu, v3, d);
            int   oi1 = __shfl_xor_sync(0xffffffffu, i1, d);
            int   oi2 = __shfl_xor_sync(0xffffffffu, i2, d);
            int   oi3 = __shfl_xor_sync(0xffffffffu, i3, d);
            ins3(ov1, oi1, v1, i1, v2, i2, v3, i3);
            ins3(ov2, oi2, v1, i1, v2, i2, v3, i3);
            ins3(ov3, oi3, v1, i1, v2, i2, v3, i3);
        }
        float ex = expf(ax - v1), ey = expf(ay - v1);
        float s = ex + ey;
        #pragma unroll
        for (int d = 1; d < 32; d <<= 1) s += __shfl_xor_sync(0xffffffffu, s, d);
        const float inv = 1.0f / s;

        *(float2*)(out + (size_t)T_TOK * 4 + (size_t)t * E_EXP + 2 * lid) =
            make_float2(ex * inv, ey * inv);
        if (lid == 0) {
            float e2 = expf(v2 - v1);
            float cd = 1.0f / (1.0f + e2);
            *(float2*)(out + (size_t)t * 2) = make_float2(cd, e2 * cd);
            *(float2*)(out + (size_t)T_TOK * 2 + (size_t)t * 2) =
                make_float2((float)i1, (float)i2);
        }
    }
}

extern "C" void kernel_launch(void* const* d_in, const int* in_sizes, int n_in,
                              void* d_out, int out_size) {
    const float* x  = (const float*)d_in[0];
    const float* Wg = (const float*)d_in[1];
    float* out = (float*)d_out;
    (void)in_sizes; (void)n_in; (void)out_size;

    cudaFuncSetAttribute(router_main,
                         cudaFuncAttributeMaxDynamicSharedMemorySize, SMEM_TOTAL);
    prep<<<256, 256>>>(Wg);
    router_main<<<T_TOK / BM, NTH, SMEM_TOTAL>>>(x, out);
    router_fixup<<<512, 128>>>(x, Wg, out);
}

// round 9
// speedup vs baseline: 1.5199x; 1.1106x over previous
#include <cuda_runtime.h>
#include <cuda_fp16.h>
#include <cstdint>
#include <math.h>

// Router: logits = x @ Wg ; softmax ; top-2 ; renorm combine.
// x: [65536,1024] f32, Wg: [1024,64] f32.
// Out f32: [0,2T) combine | [2T,4T) idx | [4T,68T) probs.
//
// Single-product fp16 mma.sync (fp32 accum), KC=64, 2-stage smem ping-pong,
// register prefetch one chunk ahead. Logit noise sigma ~3e-4 (R7-measured
// rel_err 2.7e-4). Top-2 identity protected by exact fp32 fix-up for tokens
// with top-1/2 or 2/3 gap < 4e-3 (>13 sigma).

#define T_TOK 65536
#define D_DIM 1024
#define E_EXP 64
#define BM 128
#define KC 64
#define NKC (D_DIM / KC)   // 16
#define NTH 256
#define ASTRIDE 144        // 64 fp16 (128B) + 16B pad; conflict-free ldmatrix
#define TH_AMB 4.0e-3f
#define NEG_INF (-3.0e38f)

#define A_BYTES (BM * ASTRIDE)              // 18432
#define B_BYTES (E_EXP * ASTRIDE)           //  9216
#define STAGE_BYTES (A_BYTES + B_BYTES)     // 27648
#define SMEM_TOTAL (2 * STAGE_BYTES)        // 55296

__device__ __half g_wth[E_EXP * D_DIM];  // Wg^T fp16: [n][k]
__device__ int g_cnt;
__device__ int g_list[T_TOK];

// ---------- helpers ----------
__device__ __forceinline__ uint32_t pack2(float a, float b) {
    __half2 H = __floats2half2_rn(a, b);
    return *(uint32_t*)&H;
}

__device__ __forceinline__ void ldm4(uint32_t& r0, uint32_t& r1, uint32_t& r2,
                                     uint32_t& r3, uint32_t addr) {
    asm volatile("ldmatrix.sync.aligned.m8n8.x4.shared.b16 {%0,%1,%2,%3}, [%4];"
                 : "=r"(r0), "=r"(r1), "=r"(r2), "=r"(r3) : "r"(addr));
}

__device__ __forceinline__ void mma_f16(float* c, uint32_t a0, uint32_t a1,
                                        uint32_t a2, uint32_t a3,
                                        uint32_t b0, uint32_t b1) {
    asm volatile(
        "mma.sync.aligned.m16n8k16.row.col.f32.f16.f16.f32 "
        "{%0,%1,%2,%3}, {%4,%5,%6,%7}, {%8,%9}, {%0,%1,%2,%3};"
        : "+f"(c[0]), "+f"(c[1]), "+f"(c[2]), "+f"(c[3])
        : "r"(a0), "r"(a1), "r"(a2), "r"(a3), "r"(b0), "r"(b1));
}

__device__ __forceinline__ void ins3(float v, int i,
                                     float& v1, int& i1, float& v2, int& i2,
                                     float& v3, int& i3) {
    if (v > v1 || (v == v1 && i < i1)) {
        v3 = v2; i3 = i2; v2 = v1; i2 = i1; v1 = v; i1 = i;
    } else if (v > v2 || (v == v2 && i < i2)) {
        v3 = v2; i3 = i2; v2 = v; i2 = i;
    } else if (v > v3 || (v == v3 && i < i3)) {
        v3 = v; i3 = i;
    }
}

// ---------- prep ----------
__global__ void prep(const float* __restrict__ Wg) {
    int i = blockIdx.x * blockDim.x + threadIdx.x;  // 0..65535
    int k = i >> 6, n = i & 63;
    g_wth[n * D_DIM + k] = __float2half_rn(Wg[i]);
    if (i == 0) g_cnt = 0;
}

// ---------- pass 1 ----------
__global__ __launch_bounds__(NTH, 2)
void router_main(const float* __restrict__ x, float* __restrict__ out) {
    extern __shared__ __align__(16) unsigned char smem[];
    unsigned char* sA[2] = { smem, smem + STAGE_BYTES };
    unsigned char* sB[2] = { smem + A_BYTES, smem + STAGE_BYTES + A_BYTES };

    const int tid = threadIdx.x;
    const int w   = tid >> 5;
    const int lid = tid & 31;
    const int m0  = blockIdx.x * BM;

    float acc[8][4];
    #pragma unroll
    for (int t = 0; t < 8; ++t)
        #pragma unroll
        for (int c = 0; c < 4; ++c) acc[t][c] = 0.0f;

    const float* xbase = x + (size_t)m0 * D_DIM;

    float4 pa[8];
    float4 pb[2];

    // ---- prologue: chunk 0 -> stage 0; prefetch chunk 1 ----
    #pragma unroll
    for (int i = 0; i < 8; ++i) {
        int lin = i * NTH + tid;
        pa[i] = *(const float4*)(xbase + (size_t)(lin >> 4) * D_DIM + (lin & 15) * 4);
    }
    #pragma unroll
    for (int i = 0; i < 2; ++i) {
        int lin = i * NTH + tid;
        pb[i] = *(const float4*)(g_wth + (size_t)(lin >> 3) * D_DIM + (lin & 7) * 8);
    }
    #pragma unroll
    for (int i = 0; i < 8; ++i) {
        int lin = i * NTH + tid;
        uint32_t p0 = pack2(pa[i].x, pa[i].y);
        uint32_t p1 = pack2(pa[i].z, pa[i].w);
        *(uint2*)(sA[0] + (lin >> 4) * ASTRIDE + (lin & 15) * 8) = make_uint2(p0, p1);
    }
    #pragma unroll
    for (int i = 0; i < 2; ++i) {
        int lin = i * NTH + tid;
        *(float4*)(sB[0] + (lin >> 3) * ASTRIDE + (lin & 7) * 16) = pb[i];
    }
    // prefetch chunk 1
    #pragma unroll
    for (int i = 0; i < 8; ++i) {
        int lin = i * NTH + tid;
        pa[i] = *(const float4*)(xbase + (size_t)(lin >> 4) * D_DIM + KC + (lin & 15) * 4);
    }
    #pragma unroll
    for (int i = 0; i < 2; ++i) {
        int lin = i * NTH + tid;
        pb[i] = *(const float4*)(g_wth + (size_t)(lin >> 3) * D_DIM + KC + (lin & 7) * 8);
    }

    for (int kt = 0; kt < NKC; ++kt) {
        const int cur = kt & 1;
        if (kt + 1 < NKC) {
            const int nxt = (kt + 1) & 1;
            #pragma unroll
            for (int i = 0; i < 8; ++i) {
                int lin = i * NTH + tid;
                uint32_t p0 = pack2(pa[i].x, pa[i].y);
                uint32_t p1 = pack2(pa[i].z, pa[i].w);
                *(uint2*)(sA[nxt] + (lin >> 4) * ASTRIDE + (lin & 15) * 8) =
                    make_uint2(p0, p1);
            }
            #pragma unroll
            for (int i = 0; i < 2; ++i) {
                int lin = i * NTH + tid;
                *(float4*)(sB[nxt] + (lin >> 3) * ASTRIDE + (lin & 7) * 16) = pb[i];
            }
            if (kt + 2 < NKC) {
                const int k0 = (kt + 2) * KC;
                #pragma unroll
                for (int i = 0; i < 8; ++i) {
                    int lin = i * NTH + tid;
                    pa[i] = *(const float4*)(xbase + (size_t)(lin >> 4) * D_DIM
                                             + k0 + (lin & 15) * 4);
                }
                #pragma unroll
                for (int i = 0; i < 2; ++i) {
                    int lin = i * NTH + tid;
                    pb[i] = *(const float4*)(g_wth + (size_t)(lin >> 3) * D_DIM
                                             + k0 + (lin & 7) * 8);
                }
            }
        }
        __syncthreads();

        const uint32_t sAu = (uint32_t)__cvta_generic_to_shared(sA[cur]);
        const uint32_t sBu = (uint32_t)__cvta_generic_to_shared(sB[cur]);
        const int m = lid >> 3, r = lid & 7;

        #pragma unroll
        for (int ks = 0; ks < 4; ++ks) {
            uint32_t a0, a1, a2, a3;
            {
                uint32_t addr = sAu + (w * 16 + (m & 1) * 8 + r) * ASTRIDE
                              + (ks * 16 + (m >> 1) * 8) * 2;
                ldm4(a0, a1, a2, a3, addr);
            }
            uint32_t b[16];
            #pragma unroll
            for (int j = 0; j < 4; ++j) {
                uint32_t boff = (j * 16 + (m >> 1) * 8 + r) * ASTRIDE
                              + (ks * 16 + (m & 1) * 8) * 2;
                ldm4(b[4 * j], b[4 * j + 1], b[4 * j + 2], b[4 * j + 3], sBu + boff);
            }
            #pragma unroll
            for (int t = 0; t < 8; ++t)
                mma_f16(acc[t], a0, a1, a2, a3, b[2 * t], b[2 * t + 1]);
        }
        __syncthreads();
    }

    // ---------- fused epilogue ----------
    const int q = lid >> 2;
    const int c = lid & 3;

    #pragma unroll
    for (int rr = 0; rr < 2; ++rr) {
        float v1 = NEG_INF, v2 = NEG_INF, v3 = NEG_INF;
        int   i1 = 0, i2 = 0, i3 = 0;
        #pragma unroll
        for (int t = 0; t < 8; ++t) {
            ins3(acc[t][rr * 2 + 0], t * 8 + c * 2 + 0, v1, i1, v2, i2, v3, i3);
            ins3(acc[t][rr * 2 + 1], t * 8 + c * 2 + 1, v1, i1, v2, i2, v3, i3);
        }
        #pragma unroll
        for (int d = 1; d <= 2; d <<= 1) {
            float ov1 = __shfl_xor_sync(0xffffffffu, v1, d);
            float ov2 = __shfl_xor_sync(0xffffffffu, v2, d);
            float ov3 = __shfl_xor_sync(0xffffffffu, v3, d);
            int   oi1 = __shfl_xor_sync(0xffffffffu, i1, d);
            int   oi2 = __shfl_xor_sync(0xffffffffu, i2, d);
            int   oi3 = __shfl_xor_sync(0xffffffffu, i3, d);
            ins3(ov1, oi1, v1, i1, v2, i2, v3, i3);
            ins3(ov2, oi2, v1, i1, v2, i2, v3, i3);
            ins3(ov3, oi3, v1, i1, v2, i2, v3, i3);
        }
        float s = 0.0f;
        #pragma unroll
        for (int t = 0; t < 8; ++t) {
            float e0 = expf(acc[t][rr * 2 + 0] - v1);
            float e1 = expf(acc[t][rr * 2 + 1] - v1);
            acc[t][rr * 2 + 0] = e0;
            acc[t][rr * 2 + 1] = e1;
            s += e0 + e1;
        }
        s += __shfl_xor_sync(0xffffffffu, s, 1);
        s += __shfl_xor_sync(0xffffffffu, s, 2);
        const float inv = 1.0f / s;

        const int gt = m0 + w * 16 + q + rr * 8;
        float* pr = out + (size_t)T_TOK * 4 + (size_t)gt * E_EXP;
        #pragma unroll
        for (int t = 0; t < 8; ++t) {
            *(float2*)(pr + t * 8 + c * 2) =
                make_float2(acc[t][rr * 2] * inv, acc[t][rr * 2 + 1] * inv);
        }
        if (c == 0) {
            float e2 = expf(v2 - v1);
            float cd = 1.0f / (1.0f + e2);
            *(float2*)(out + (size_t)gt * 2) = make_float2(cd, e2 * cd);
            *(float2*)(out + (size_t)T_TOK * 2 + (size_t)gt * 2) =
                make_float2((float)i1, (float)i2);
            if ((v1 - v2 < TH_AMB) || (v2 - v3 < TH_AMB)) {
                int p = atomicAdd(&g_cnt, 1);
                g_list[p] = gt;
            }
        }
    }
}

// ---------- pass 2: exact fp32 fix-up ----------
__global__ __launch_bounds__(128)
void router_fixup(const float* __restrict__ x, const float* __restrict__ Wg,
                  float* __restrict__ out) {
    const int lid = threadIdx.x & 31;
    const int gw  = (blockIdx.x * blockDim.x + threadIdx.x) >> 5;
    const int nw  = (gridDim.x * blockDim.x) >> 5;
    const int cnt = g_cnt;
    const float2* W2 = (const float2*)Wg;

    for (int idx = gw; idx < cnt; idx += nw) {
        const int t = g_list[idx];
        const float* xr = x + (size_t)t * D_DIM;
        float ax = 0.0f, ay = 0.0f;
        for (int k0 = 0; k0 < D_DIM; k0 += 32) {
            float xv = xr[k0 + lid];
            #pragma unroll
            for (int kk = 0; kk < 32; ++kk) {
                float v = __shfl_sync(0xffffffffu, xv, kk);
                float2 wv = W2[(size_t)(k0 + kk) * 32 + lid];
                ax = fmaf(v, wv.x, ax);
                ay = fmaf(v, wv.y, ay);
            }
        }
        float v1 = NEG_INF, v2 = NEG_INF, v3 = NEG_INF;
        int   i1 = 0, i2 = 0, i3 = 0;
        ins3(ax, 2 * lid + 0, v1, i1, v2, i2, v3, i3);
        ins3(ay, 2 * lid + 1, v1, i1, v2, i2, v3, i3);
        #pragma unroll
        for (int d = 1; d < 32; d <<= 1) {
            float ov1 = __shfl_xor_sync(0xffffffffu, v1, d);
            float ov2 = __shfl_xor_sync(0xffffffffu, v2, d);
            float ov3 = __shfl_xor_sync(0xffffffffu, v3, d);
            int   oi1 = __shfl_xor_sync(0xffffffffu, i1, d);
            int   oi2 = __shfl_xor_sync(0xffffffffu, i2, d);
            int   oi3 = __shfl_xor_sync(0xffffffffu, i3, d);
            ins3(ov1, oi1, v1, i1, v2, i2, v3, i3);
            ins3(ov2, oi2, v1, i1, v2, i2, v3, i3);
            ins3(ov3, oi3, v1, i1, v2, i2, v3, i3);
        }
        float ex = expf(ax - v1), ey = expf(ay - v1);
        float s = ex + ey;
        #pragma unroll
        for (int d = 1; d < 32; d <<= 1) s += __shfl_xor_sync(0xffffffffu, s, d);
        const float inv = 1.0f / s;

        *(float2*)(out + (size_t)T_TOK * 4 + (size_t)t * E_EXP + 2 * lid) =
            make_float2(ex * inv, ey * inv);
        if (lid == 0) {
            float e2 = expf(v2 - v1);
            float cd = 1.0f / (1.0f + e2);
            *(float2*)(out + (size_t)t * 2) = make_float2(cd, e2 * cd);
            *(float2*)(out + (size_t)T_TOK * 2 + (size_t)t * 2) =
                make_float2((float)i1, (float)i2);
        }
    }
}

extern "C" void kernel_launch(void* const* d_in, const int* in_sizes, int n_in,
                              void* d_out, int out_size) {
    const float* x  = (const float*)d_in[0];
    const float* Wg = (const float*)d_in[1];
    float* out = (float*)d_out;
    (void)in_sizes; (void)n_in; (void)out_size;

    cudaFuncSetAttribute(router_main,
                         cudaFuncAttributeMaxDynamicSharedMemorySize, SMEM_TOTAL);
    prep<<<256, 256>>>(Wg);
    router_main<<<T_TOK / BM, NTH, SMEM_TOTAL>>>(x, out);
    router_fixup<<<512, 128>>>(x, Wg, out);
}

// round 10
// speedup vs baseline: 1.6389x; 1.0783x over previous
#include <cuda_runtime.h>
#include <cuda_fp16.h>
#include <cstdint>
#include <math.h>

// Router: logits = x @ Wg ; softmax ; top-2 ; renorm combine.
// x: [65536,1024] f32, Wg: [1024,64] f32.
// Out f32: [0,2T) combine | [2T,4T) idx | [4T,68T) probs.
//
// Single-product fp16 mma.sync (fp32 accum), KC=64, 3-stage rotating smem
// with ONE __syncthreads per chunk, register prefetch one chunk ahead.
// Exact fp32 fix-up for tokens with top-1/2 or 2/3 gap < 4e-3.

#define T_TOK 65536
#define D_DIM 1024
#define E_EXP 64
#define BM 128
#define KC 64
#define NKC (D_DIM / KC)   // 16
#define NTH 256
#define ASTRIDE 144        // 64 fp16 (128B) + 16B pad; conflict-free ldmatrix
#define TH_AMB 4.0e-3f
#define NEG_INF (-3.0e38f)

#define A_BYTES (BM * ASTRIDE)              // 18432
#define B_BYTES (E_EXP * ASTRIDE)           //  9216
#define STAGE_BYTES (A_BYTES + B_BYTES)     // 27648
#define NSTAGE 3
#define SMEM_TOTAL (NSTAGE * STAGE_BYTES)   // 82944

__device__ __half g_wth[E_EXP * D_DIM];  // Wg^T fp16: [n][k]
__device__ int g_cnt;
__device__ int g_list[T_TOK];

// ---------- helpers ----------
__device__ __forceinline__ uint32_t pack2(float a, float b) {
    __half2 H = __floats2half2_rn(a, b);
    return *(uint32_t*)&H;
}

__device__ __forceinline__ void ldm4(uint32_t& r0, uint32_t& r1, uint32_t& r2,
                                     uint32_t& r3, uint32_t addr) {
    asm volatile("ldmatrix.sync.aligned.m8n8.x4.shared.b16 {%0,%1,%2,%3}, [%4];"
                 : "=r"(r0), "=r"(r1), "=r"(r2), "=r"(r3) : "r"(addr));
}

__device__ __forceinline__ void mma_f16(float* c, uint32_t a0, uint32_t a1,
                                        uint32_t a2, uint32_t a3,
                                        uint32_t b0, uint32_t b1) {
    asm volatile(
        "mma.sync.aligned.m16n8k16.row.col.f32.f16.f16.f32 "
        "{%0,%1,%2,%3}, {%4,%5,%6,%7}, {%8,%9}, {%0,%1,%2,%3};"
        : "+f"(c[0]), "+f"(c[1]), "+f"(c[2]), "+f"(c[3])
        : "r"(a0), "r"(a1), "r"(a2), "r"(a3), "r"(b0), "r"(b1));
}

__device__ __forceinline__ void ins3(float v, int i,
                                     float& v1, int& i1, float& v2, int& i2,
                                     float& v3, int& i3) {
    if (v > v1 || (v == v1 && i < i1)) {
        v3 = v2; i3 = i2; v2 = v1; i2 = i1; v1 = v; i1 = i;
    } else if (v > v2 || (v == v2 && i < i2)) {
        v3 = v2; i3 = i2; v2 = v; i2 = i;
    } else if (v > v3 || (v == v3 && i < i3)) {
        v3 = v; i3 = i;
    }
}

// ---------- prep ----------
__global__ void prep(const float* __restrict__ Wg) {
    int i = blockIdx.x * blockDim.x + threadIdx.x;  // 0..65535
    int k = i >> 6, n = i & 63;
    g_wth[n * D_DIM + k] = __float2half_rn(Wg[i]);
    if (i == 0) g_cnt = 0;
}

// ---------- pass 1 ----------
__global__ __launch_bounds__(NTH, 2)
void router_main(const float* __restrict__ x, float* __restrict__ out) {
    extern __shared__ __align__(16) unsigned char smem[];

    const int tid = threadIdx.x;
    const int w   = tid >> 5;
    const int lid = tid & 31;
    const int m0  = blockIdx.x * BM;

    float acc[8][4];
    #pragma unroll
    for (int t = 0; t < 8; ++t)
        #pragma unroll
        for (int c = 0; c < 4; ++c) acc[t][c] = 0.0f;

    const float* xbase = x + (size_t)m0 * D_DIM;

    float4 pa[8];
    float4 pb[2];

    // A map: 8 float4/thread, row = lin>>4, c4 = lin&15
    // B map: 2 float4/thread, row = lin>>3, c = lin&7

    // ---- prologue: chunk 0 -> stage 0; load chunk 1 into regs ----
    #pragma unroll
    for (int i = 0; i < 8; ++i) {
        int lin = i * NTH + tid;
        pa[i] = *(const float4*)(xbase + (size_t)(lin >> 4) * D_DIM + (lin & 15) * 4);
    }
    #pragma unroll
    for (int i = 0; i < 2; ++i) {
        int lin = i * NTH + tid;
        pb[i] = *(const float4*)(g_wth + (size_t)(lin >> 3) * D_DIM + (lin & 7) * 8);
    }
    {
        unsigned char* sA0 = smem;
        unsigned char* sB0 = smem + A_BYTES;
        #pragma unroll
        for (int i = 0; i < 8; ++i) {
            int lin = i * NTH + tid;
            uint32_t p0 = pack2(pa[i].x, pa[i].y);
            uint32_t p1 = pack2(pa[i].z, pa[i].w);
            *(uint2*)(sA0 + (lin >> 4) * ASTRIDE + (lin & 15) * 8) = make_uint2(p0, p1);
        }
        #pragma unroll
        for (int i = 0; i < 2; ++i) {
            int lin = i * NTH + tid;
            *(float4*)(sB0 + (lin >> 3) * ASTRIDE + (lin & 7) * 16) = pb[i];
        }
    }
    // load chunk 1 into regs
    #pragma unroll
    for (int i = 0; i < 8; ++i) {
        int lin = i * NTH + tid;
        pa[i] = *(const float4*)(xbase + (size_t)(lin >> 4) * D_DIM + KC + (lin & 15) * 4);
    }
    #pragma unroll
    for (int i = 0; i < 2; ++i) {
        int lin = i * NTH + tid;
        pb[i] = *(const float4*)(g_wth + (size_t)(lin >> 3) * D_DIM + KC + (lin & 7) * 8);
    }

    int s_cur = 0;   // stage holding chunk kt
    int s_nxt = 1;   // stage to write chunk kt+1

    for (int kt = 0; kt < NKC; ++kt) {
        if (kt + 1 < NKC) {
            unsigned char* sAn = smem + s_nxt * STAGE_BYTES;
            unsigned char* sBn = sAn + A_BYTES;
            #pragma unroll
            for (int i = 0; i < 8; ++i) {
                int lin = i * NTH + tid;
                uint32_t p0 = pack2(pa[i].x, pa[i].y);
                uint32_t p1 = pack2(pa[i].z, pa[i].w);
                *(uint2*)(sAn + (lin >> 4) * ASTRIDE + (lin & 15) * 8) =
                    make_uint2(p0, p1);
            }
            #pragma unroll
            for (int i = 0; i < 2; ++i) {
                int lin = i * NTH + tid;
                *(float4*)(sBn + (lin >> 3) * ASTRIDE + (lin & 7) * 16) = pb[i];
            }
            if (kt + 2 < NKC) {
                const int k0 = (kt + 2) * KC;
                #pragma unroll
                for (int i = 0; i < 8; ++i) {
                    int lin = i * NTH + tid;
                    pa[i] = *(const float4*)(xbase + (size_t)(lin >> 4) * D_DIM
                                             + k0 + (lin & 15) * 4);
                }
                #pragma unroll
                for (int i = 0; i < 2; ++i) {
                    int lin = i * NTH + tid;
                    pb[i] = *(const float4*)(g_wth + (size_t)(lin >> 3) * D_DIM
                                             + k0 + (lin & 7) * 8);
                }
            }
        }
        __syncthreads();   // single barrier per chunk (3-stage rotation)

        const uint32_t sAu = (uint32_t)__cvta_generic_to_shared(smem + s_cur * STAGE_BYTES);
        const uint32_t sBu = sAu + A_BYTES;
        const int m = lid >> 3, r = lid & 7;

        #pragma unroll
        for (int ks = 0; ks < 4; ++ks) {
            uint32_t a0, a1, a2, a3;
            {
                uint32_t addr = sAu + (w * 16 + (m & 1) * 8 + r) * ASTRIDE
                              + (ks * 16 + (m >> 1) * 8) * 2;
                ldm4(a0, a1, a2, a3, addr);
            }
            uint32_t b[16];
            #pragma unroll
            for (int j = 0; j < 4; ++j) {
                uint32_t boff = (j * 16 + (m >> 1) * 8 + r) * ASTRIDE
                              + (ks * 16 + (m & 1) * 8) * 2;
                ldm4(b[4 * j], b[4 * j + 1], b[4 * j + 2], b[4 * j + 3], sBu + boff);
            }
            #pragma unroll
            for (int t = 0; t < 8; ++t)
                mma_f16(acc[t], a0, a1, a2, a3, b[2 * t], b[2 * t + 1]);
        }

        s_cur = s_nxt;
        s_nxt = (s_nxt == NSTAGE - 1) ? 0 : s_nxt + 1;
    }

    // ---------- fused epilogue ----------
    const int q = lid >> 2;
    const int c = lid & 3;

    #pragma unroll
    for (int rr = 0; rr < 2; ++rr) {
        float v1 = NEG_INF, v2 = NEG_INF, v3 = NEG_INF;
        int   i1 = 0, i2 = 0, i3 = 0;
        #pragma unroll
        for (int t = 0; t < 8; ++t) {
            ins3(acc[t][rr * 2 + 0], t * 8 + c * 2 + 0, v1, i1, v2, i2, v3, i3);
            ins3(acc[t][rr * 2 + 1], t * 8 + c * 2 + 1, v1, i1, v2, i2, v3, i3);
        }
        #pragma unroll
        for (int d = 1; d <= 2; d <<= 1) {
            float ov1 = __shfl_xor_sync(0xffffffffu, v1, d);
            float ov2 = __shfl_xor_sync(0xffffffffu, v2, d);
            float ov3 = __shfl_xor_sync(0xffffffffu, v3, d);
            int   oi1 = __shfl_xor_sync(0xffffffffu, i1, d);
            int   oi2 = __shfl_xor_sync(0xffffffffu, i2, d);
            int   oi3 = __shfl_xor_sync(0xffffffffu, i3, d);
            ins3(ov1, oi1, v1, i1, v2, i2, v3, i3);
            ins3(ov2, oi2, v1, i1, v2, i2, v3, i3);
            ins3(ov3, oi3, v1, i1, v2, i2, v3, i3);
        }
        float s = 0.0f;
        #pragma unroll
        for (int t = 0; t < 8; ++t) {
            float e0 = __expf(acc[t][rr * 2 + 0] - v1);
            float e1 = __expf(acc[t][rr * 2 + 1] - v1);
            acc[t][rr * 2 + 0] = e0;
            acc[t][rr * 2 + 1] = e1;
            s += e0 + e1;
        }
        s += __shfl_xor_sync(0xffffffffu, s, 1);
        s += __shfl_xor_sync(0xffffffffu, s, 2);
        const float inv = 1.0f / s;

        const int gt = m0 + w * 16 + q + rr * 8;
        float* pr = out + (size_t)T_TOK * 4 + (size_t)gt * E_EXP;
        #pragma unroll
        for (int t = 0; t < 8; ++t) {
            *(float2*)(pr + t * 8 + c * 2) =
                make_float2(acc[t][rr * 2] * inv, acc[t][rr * 2 + 1] * inv);
        }
        if (c == 0) {
            float e2 = __expf(v2 - v1);
            float cd = 1.0f / (1.0f + e2);
            *(float2*)(out + (size_t)gt * 2) = make_float2(cd, e2 * cd);
            *(float2*)(out + (size_t)T_TOK * 2 + (size_t)gt * 2) =
                make_float2((float)i1, (float)i2);
            if ((v1 - v2 < TH_AMB) || (v2 - v3 < TH_AMB)) {
                int p = atomicAdd(&g_cnt, 1);
                g_list[p] = gt;
            }
        }
    }
}

// ---------- pass 2: exact fp32 fix-up ----------
__global__ __launch_bounds__(128)
void router_fixup(const float* __restrict__ x, const float* __restrict__ Wg,
                  float* __restrict__ out) {
    const int lid = threadIdx.x & 31;
    const int gw  = (blockIdx.x * blockDim.x + threadIdx.x) >> 5;
    const int nw  = (gridDim.x * blockDim.x) >> 5;
    const int cnt = g_cnt;
    const float2* W2 = (const float2*)Wg;

    for (int idx = gw; idx < cnt; idx += nw) {
        const int t = g_list[idx];
        const float* xr = x + (size_t)t * D_DIM;
        float ax = 0.0f, ay = 0.0f;
        for (int k0 = 0; k0 < D_DIM; k0 += 32) {
            float xv = xr[k0 + lid];
            #pragma unroll
            for (int kk = 0; kk < 32; ++kk) {
                float v = __shfl_sync(0xffffffffu, xv, kk);
                float2 wv = W2[(size_t)(k0 + kk) * 32 + lid];
                ax = fmaf(v, wv.x, ax);
                ay = fmaf(v, wv.y, ay);
            }
        }
        float v1 = NEG_INF, v2 = NEG_INF, v3 = NEG_INF;
        int   i1 = 0, i2 = 0, i3 = 0;
        ins3(ax, 2 * lid + 0, v1, i1, v2, i2, v3, i3);
        ins3(ay, 2 * lid + 1, v1, i1, v2, i2, v3, i3);
        #pragma unroll
        for (int d = 1; d < 32; d <<= 1) {
            float ov1 = __shfl_xor_sync(0xffffffffu, v1, d);
            float ov2 = __shfl_xor_sync(0xffffffffu, v2, d);
            float ov3 = __shfl_xor_sync(0xffffffffu, v3, d);
            int   oi1 = __shfl_xor_sync(0xffffffffu, i1, d);
            int   oi2 = __shfl_xor_sync(0xffffffffu, i2, d);
            int   oi3 = __shfl_xor_sync(0xffffffffu, i3, d);
            ins3(ov1, oi1, v1, i1, v2, i2, v3, i3);
            ins3(ov2, oi2, v1, i1, v2, i2, v3, i3);
            ins3(ov3, oi3, v1, i1, v2, i2, v3, i3);
        }
        float ex = expf(ax - v1), ey = expf(ay - v1);
        float s = ex + ey;
        #pragma unroll
        for (int d = 1; d < 32; d <<= 1) s += __shfl_xor_sync(0xffffffffu, s, d);
        const float inv = 1.0f / s;

        *(float2*)(out + (size_t)T_TOK * 4 + (size_t)t * E_EXP + 2 * lid) =
            make_float2(ex * inv, ey * inv);
        if (lid == 0) {
            float e2 = expf(v2 - v1);
            float cd = 1.0f / (1.0f + e2);
            *(float2*)(out + (size_t)t * 2) = make_float2(cd, e2 * cd);
            *(float2*)(out + (size_t)T_TOK * 2 + (size_t)t * 2) =
                make_float2((float)i1, (float)i2);
        }
    }
}

extern "C" void kernel_launch(void* const* d_in, const int* in_sizes, int n_in,
                              void* d_out, int out_size) {
    const float* x  = (const float*)d_in[0];
    const float* Wg = (const float*)d_in[1];
    float* out = (float*)d_out;
    (void)in_sizes; (void)n_in; (void)out_size;

    cudaFuncSetAttribute(router_main,
                         cudaFuncAttributeMaxDynamicSharedMemorySize, SMEM_TOTAL);
    prep<<<256, 256>>>(Wg);
    router_main<<<T_TOK / BM, NTH, SMEM_TOTAL>>>(x, out);
    router_fixup<<<512, 128>>>(x, Wg, out);
}